// round 15
// baseline (speedup 1.0000x reference)
#include <cuda_runtime.h>
#include <cstdint>

// Problem constants
#define MROWS   65536
#define NSPL    32          // spline groups per row
#define GPB     4           // groups per block
#define BM      64          // rows per block
#define THREADS 256         // 8 warps: warp = (group, row-half)
#define KTOT    49          // 48 data k + bias row (A[48]=1)
#define WS_KS   144         // Ws floats per k: 4 groups x 36 (33 + 3 pad)
#define AST     66          // A row stride (64 rows + 2 pad)
#define WS_F    (KTOT * WS_KS)          // 7056
#define AS_F    (KTOT * AST + 2)        // 3236 (pad -> stash 16B aligned)
#define STASH_U (17 * 256)              // 17 pairs x (8 warps x 32 warp-local rows)
#define SMEM_BYTES ((WS_F + AS_F) * 4 + STASH_U * 8)   // 75984 -> 3 blocks/SM

// ---------- packed f32x2 helpers ----------
__device__ __forceinline__ unsigned long long pack2(float a) {
    unsigned long long r;
    asm("mov.b64 %0, {%1, %1};" : "=l"(r) : "f"(a));
    return r;
}
__device__ __forceinline__ void ffma2(unsigned long long& d,
                                      unsigned long long a,
                                      unsigned long long b) {
    asm("fma.rn.f32x2 %0, %1, %2, %0;" : "+l"(d) : "l"(a), "l"(b));
}

__device__ __forceinline__ float softplus_fast(float x) {
    return __logf(1.0f + __expf(x)) + 0.001f;
}

// ---------- quadratic spline (per (m,n) pair), MUFU fast-math ----------
// getacc(p) returns packed pair (y[2p], y[2p+1]); y[0..16]=unnorm heights,
// y[17..32]=unnorm widths; getacc(16) hi = pad (ignored).
template <typename F>
__device__ __forceinline__ float spline_eval(F getacc, float input, float& x_out) {
    float h[17], w[16];

#pragma unroll
    for (int p = 0; p < 8; p++) {
        unsigned long long v = getacc(p);
        h[2 * p]     = softplus_fast(__uint_as_float((unsigned int)v));
        h[2 * p + 1] = softplus_fast(__uint_as_float((unsigned int)(v >> 32)));
    }
    unsigned long long v8 = getacc(8);
    h[16] = softplus_fast(__uint_as_float((unsigned int)v8));

    float esum;
    w[0] = __expf(__uint_as_float((unsigned int)(v8 >> 32)));
    esum = w[0];
#pragma unroll
    for (int p = 9; p <= 15; p++) {
        unsigned long long v = getacc(p);
        float e0 = __expf(__uint_as_float((unsigned int)v));
        float e1 = __expf(__uint_as_float((unsigned int)(v >> 32)));
        w[2 * p - 17] = e0;
        w[2 * p - 16] = e1;
        esum += e0 + e1;
    }
    {
        unsigned long long v = getacc(16);
        float e0 = __expf(__uint_as_float((unsigned int)v));
        w[15] = e0;
        esum += e0;
    }

    float inv = __fdividef(1.0f, esum);
#pragma unroll
    for (int i = 0; i < 16; i++) w[i] = 0.001f + 0.984f * (w[i] * inv);

    float area2 = 0.0f;
#pragma unroll
    for (int i = 0; i < 16; i++) area2 += (h[i] + h[i + 1]) * w[i];
    float hs = __fdividef(1.998f, area2);
#pragma unroll
    for (int i = 0; i < 17; i++) h[i] = 0.001f + h[i] * hs;

    float L = 0.0f, C2 = 0.0f;
    float bl = 0.0f, bw = w[0], lcdf2 = 0.0f, hl = h[0], hr = h[1];
#pragma unroll
    for (int i = 1; i <= 15; i++) {
        L  += w[i - 1];
        C2 += (h[i - 1] + h[i]) * w[i - 1];
        if (input >= L) { bl = L; bw = w[i]; lcdf2 = C2; hl = h[i]; hr = h[i + 1]; }
    }

    float aq    = 0.5f * (hr - hl) * bw;
    float bq    = hl * bw;
    float alpha = __fdividef(input - bl, bw);
    float o = aq * alpha * alpha + bq * alpha + 0.5f * lcdf2;
    x_out = fminf(fmaxf(o, 0.0f), 1.0f);
    return __logf(alpha * (hr - hl) + hl);
}

// ---------- prep: zero log_det ----------
__global__ void prep_kernel(float* __restrict__ out) {
    int tid = blockIdx.x * blockDim.x + threadIdx.x;
    if (tid < MROWS / 4)
        ((float4*)(out + (size_t)MROWS * 64))[tid] = make_float4(0.f, 0.f, 0.f, 0.f);
}

// ---------- fused GEMM + spline, half-warp pair-split ----------
// Warp w: group gw=w>>1, rows [(w&1)*32, +32). Lanes 0-15: pairs 0-7 of rows
// (2l,2l+1); lanes 16-31: pairs 8-16 of the same rows. acc = 18 u64 = 36 regs.
// Spline: one eval per thread (lane = warp-local row), pairs via warp stash.
__global__ void __launch_bounds__(THREADS, 3)
spline_main_kernel(const float* __restrict__ c, const float* __restrict__ z,
                   const float* __restrict__ W, const float* __restrict__ b,
                   float* __restrict__ out) {
    extern __shared__ float sm[];
    float* Ws = sm;                                      // [49][4][36]
    float* As = sm + WS_F;                               // [49][66] transposed [k][row]
    unsigned long long* stash = (unsigned long long*)(sm + WS_F + AS_F);  // [17][256]

    const int t       = threadIdx.x;
    const int g       = blockIdx.x;                      // 0..7
    const int rowbase = blockIdx.y * BM;

    // Ws fill: y-coeff j of group gj at k (k=48 -> bias). [k][gj][j], pads 33-35.
    for (int idx = t; idx < KTOT * GPB * 33; idx += THREADS) {
        int k  = idx / (GPB * 33);
        int r  = idx - k * (GPB * 33);
        int gj = r / 33, j = r - gj * 33;
        int col = (g * GPB + gj) * 33 + j;
        float v = (k < 48) ? W[(size_t)k * 1056 + col] : b[col];
        Ws[k * WS_KS + gj * 36 + j] = v;
    }
    for (int idx = t; idx < KTOT * GPB; idx += THREADS)  // zero pad j=33 (pair-16 hi)
        Ws[(idx / GPB) * WS_KS + (idx % GPB) * 36 + 33] = 0.0f;

    // A tile transposed: k 0..31 = z[:,32:64], 32..47 = c, 48 = ones.
    for (int idx = t; idx < BM * 8; idx += THREADS) {
        int q = idx / BM, r = idx - q * BM;
        float4 v = *(const float4*)&z[(size_t)(rowbase + r) * 64 + 32 + q * 4];
        As[(q * 4 + 0) * AST + r] = v.x;
        As[(q * 4 + 1) * AST + r] = v.y;
        As[(q * 4 + 2) * AST + r] = v.z;
        As[(q * 4 + 3) * AST + r] = v.w;
    }
    for (int idx = t; idx < BM * 4; idx += THREADS) {
        int q = idx / BM, r = idx - q * BM;
        float4 v = *(const float4*)&c[(size_t)(rowbase + r) * 16 + q * 4];
        As[(32 + q * 4 + 0) * AST + r] = v.x;
        As[(32 + q * 4 + 1) * AST + r] = v.y;
        As[(32 + q * 4 + 2) * AST + r] = v.z;
        As[(32 + q * 4 + 3) * AST + r] = v.w;
    }
    for (int idx = t; idx < BM; idx += THREADS) As[48 * AST + idx] = 1.0f;
    __syncthreads();

    const int w_id = t >> 5, lane = t & 31;
    const int gw = w_id >> 1, rowhalf = w_id & 1;
    const int h1 = lane >> 4, l16 = lane & 15;
    const int lr = rowhalf * 32 + 2 * l16;     // GEMM rows lr, lr+1 (block-local)
    const int gn = g * GPB + gw;               // global spline index

    // spline input (this thread's single eval), hoisted to hide LDG latency
    const int myrow = rowbase + rowhalf * 32 + lane;
    float zin = z[(size_t)myrow * 64 + gn];

    // g==0 writes x[:, :32] = z2 from the As tile
    if (g == 0) {
        int r = t >> 2, c0 = (t & 3) * 8;
        float vv[8];
#pragma unroll
        for (int q = 0; q < 8; q++) vv[q] = As[(c0 + q) * AST + r];
        float4* dst = (float4*)&out[(size_t)(rowbase + r) * 64 + c0];
        dst[0] = make_float4(vv[0], vv[1], vv[2], vv[3]);
        dst[1] = make_float4(vv[4], vv[5], vv[6], vv[7]);
    }

    // ---- GEMM: 9 pairs x 2 rows (half1 also owns pair slot 16) ----
    const float* wbase = Ws + gw * 36 + h1 * 16;   // h0: pairs 0-7; h1: pairs 8-15 (+16)
    unsigned long long acc0[9], acc1[9];
#pragma unroll
    for (int p = 0; p < 9; p++) { acc0[p] = 0ull; acc1[p] = 0ull; }

#pragma unroll 7
    for (int k = 0; k < KTOT; k++) {
        unsigned long long araw = *(const unsigned long long*)(As + k * AST + lr);
        unsigned long long ap0 = pack2(__uint_as_float((unsigned int)araw));
        unsigned long long ap1 = pack2(__uint_as_float((unsigned int)(araw >> 32)));
        const float* wrow = wbase + k * WS_KS;
#pragma unroll
        for (int i = 0; i < 4; i++) {       // 4x LDS.128, 2-address per warp
            ulonglong2 wv = *(const ulonglong2*)(wrow + i * 4);
            ffma2(acc0[2 * i],     ap0, wv.x);
            ffma2(acc1[2 * i],     ap1, wv.x);
            ffma2(acc0[2 * i + 1], ap0, wv.y);
            ffma2(acc1[2 * i + 1], ap1, wv.y);
        }
        if (h1) {                            // pair 16 (half1 only)
            unsigned long long wt = *(const unsigned long long*)(wrow + 16);
            ffma2(acc0[8], ap0, wt);
            ffma2(acc1[8], ap1, wt);
        }
    }

    // ---- stash: warp region w_id*32, WARP-LOCAL rows 2*l16, 2*l16+1 ----
    // (fixed: do NOT add rowhalf*32 here — reader indexes by lane 0..31)
    const int pbase = h1 * 8;                // h0 -> p 0-7, h1 -> p 8-15 (+16)
    unsigned long long* srow = stash + w_id * 32 + 2 * l16;
#pragma unroll
    for (int i = 0; i < 8; i++) {
        ulonglong2 v; v.x = acc0[i]; v.y = acc1[i];
        *(ulonglong2*)(srow + (pbase + i) * 256) = v;
    }
    if (h1) {
        ulonglong2 v; v.x = acc0[8]; v.y = acc1[8];
        *(ulonglong2*)(srow + 16 * 256) = v;
    }
    __syncwarp();

    // ---- spline: one eval per thread, pairs streamed from warp stash ----
    const unsigned long long* spr = stash + w_id * 32 + lane;
    float x, ld;
    ld = spline_eval([&](int p) { return spr[p * 256]; }, zin, x);

    // ---- staged epilogue (buf overlays stash after full-block barrier) ----
    __syncthreads();
    float2* buf = (float2*)stash;            // [4 groups][64 rows]
    buf[gw * BM + rowhalf * 32 + lane] = make_float2(x, ld);
    __syncthreads();

    {   // x writeout: 4 cols [32+g*4, +4) per row, 16B segments per 4 lanes
        int r = t >> 2, q = t & 3;
        out[(size_t)(rowbase + r) * 64 + 32 + g * GPB + q] = buf[q * BM + r].x;
    }
    if (t < BM) {                            // log_det: reduce 4 groups, 1 atomic/row
        float s = buf[t].y + buf[BM + t].y + buf[2 * BM + t].y + buf[3 * BM + t].y;
        atomicAdd(&out[(size_t)MROWS * 64 + rowbase + t], s);
    }
}

extern "C" void kernel_launch(void* const* d_in, const int* in_sizes, int n_in,
                              void* d_out, int out_size) {
    const float* c = (const float*)d_in[0];   // (65536, 16)
    const float* z = (const float*)d_in[1];   // (65536, 64)
    const float* W = (const float*)d_in[2];   // (48, 1056)
    const float* b = (const float*)d_in[3];   // (1056,)
    float* out = (float*)d_out;               // 65536*64 (x) + 65536 (log_det)

    cudaFuncSetAttribute(spline_main_kernel,
                         cudaFuncAttributeMaxDynamicSharedMemorySize, SMEM_BYTES);

    prep_kernel<<<(MROWS / 4 + 255) / 256, 256>>>(out);

    dim3 grid(NSPL / GPB, MROWS / BM);        // (8, 1024)
    spline_main_kernel<<<grid, THREADS, SMEM_BYTES>>>(c, z, W, b, out);
}

// round 16
// speedup vs baseline: 1.0523x; 1.0523x over previous
#include <cuda_runtime.h>
#include <cstdint>

// Problem constants
#define MROWS   65536
#define NSPL    32          // spline groups per row
#define GPB     4           // groups per block
#define BM      64          // rows per block
#define THREADS 256         // 8 warps: warp = (group, row-half)
#define KTOT    49          // 48 data k + bias row (A[48]=1)
#define WS_KS   144         // Ws floats per k: 4 groups x 36 (33 + 3 pad)
#define AST     66          // A row stride (64 rows + 2 pad)
#define WS_F    (KTOT * WS_KS)          // 7056
#define AS_F    (KTOT * AST + 2)        // 3236 (pad -> stash 16B aligned)
#define STASH_U (17 * 256)              // 17 pairs x (8 warps x 32 warp-local rows)
#define SMEM_BYTES ((WS_F + AS_F) * 4 + STASH_U * 8)   // 75984 -> 3 blocks/SM

// ---------- packed f32x2 helpers ----------
__device__ __forceinline__ unsigned long long pack2(float a) {
    unsigned long long r;
    asm("mov.b64 %0, {%1, %1};" : "=l"(r) : "f"(a));
    return r;
}
__device__ __forceinline__ void ffma2(unsigned long long& d,
                                      unsigned long long a,
                                      unsigned long long b) {
    asm("fma.rn.f32x2 %0, %1, %2, %0;" : "+l"(d) : "l"(a), "l"(b));
}

__device__ __forceinline__ float softplus_fast(float x) {
    return __logf(1.0f + __expf(x)) + 0.001f;
}

// ---------- quadratic spline (per (m,n) pair), MUFU fast-math ----------
// getacc(p) returns packed pair (y[2p], y[2p+1]); y[0..16]=unnorm heights,
// y[17..32]=unnorm widths; getacc(16) hi = pad (ignored).
template <typename F>
__device__ __forceinline__ float spline_eval(F getacc, float input, float& x_out) {
    float h[17], w[16];

#pragma unroll
    for (int p = 0; p < 8; p++) {
        unsigned long long v = getacc(p);
        h[2 * p]     = softplus_fast(__uint_as_float((unsigned int)v));
        h[2 * p + 1] = softplus_fast(__uint_as_float((unsigned int)(v >> 32)));
    }
    unsigned long long v8 = getacc(8);
    h[16] = softplus_fast(__uint_as_float((unsigned int)v8));

    float esum;
    w[0] = __expf(__uint_as_float((unsigned int)(v8 >> 32)));
    esum = w[0];
#pragma unroll
    for (int p = 9; p <= 15; p++) {
        unsigned long long v = getacc(p);
        float e0 = __expf(__uint_as_float((unsigned int)v));
        float e1 = __expf(__uint_as_float((unsigned int)(v >> 32)));
        w[2 * p - 17] = e0;
        w[2 * p - 16] = e1;
        esum += e0 + e1;
    }
    {
        unsigned long long v = getacc(16);
        float e0 = __expf(__uint_as_float((unsigned int)v));
        w[15] = e0;
        esum += e0;
    }

    float inv = __fdividef(1.0f, esum);
#pragma unroll
    for (int i = 0; i < 16; i++) w[i] = 0.001f + 0.984f * (w[i] * inv);

    float area2 = 0.0f;
#pragma unroll
    for (int i = 0; i < 16; i++) area2 += (h[i] + h[i + 1]) * w[i];
    float hs = __fdividef(1.998f, area2);
#pragma unroll
    for (int i = 0; i < 17; i++) h[i] = 0.001f + h[i] * hs;

    float L = 0.0f, C2 = 0.0f;
    float bl = 0.0f, bw = w[0], lcdf2 = 0.0f, hl = h[0], hr = h[1];
#pragma unroll
    for (int i = 1; i <= 15; i++) {
        L  += w[i - 1];
        C2 += (h[i - 1] + h[i]) * w[i - 1];
        if (input >= L) { bl = L; bw = w[i]; lcdf2 = C2; hl = h[i]; hr = h[i + 1]; }
    }

    float aq    = 0.5f * (hr - hl) * bw;
    float bq    = hl * bw;
    float alpha = __fdividef(input - bl, bw);
    float o = aq * alpha * alpha + bq * alpha + 0.5f * lcdf2;
    x_out = fminf(fmaxf(o, 0.0f), 1.0f);
    return __logf(alpha * (hr - hl) + hl);
}

// ---------- prep: zero log_det ----------
__global__ void prep_kernel(float* __restrict__ out) {
    int tid = blockIdx.x * blockDim.x + threadIdx.x;
    if (tid < MROWS / 4)
        ((float4*)(out + (size_t)MROWS * 64))[tid] = make_float4(0.f, 0.f, 0.f, 0.f);
}

// ---------- fused GEMM + spline, half-warp pair-split (branch-free k-loop) ----------
// Warp w: group gw=w>>1, rows [(w&1)*32, +32). Lanes 0-15: pairs 0-7 of rows
// (2l,2l+1); lanes 16-31: pairs 8-16. acc = 18 u64 = 36 regs.
// Pair slot 8 (wrow+16) is computed UNCONDITIONALLY by both halves (h0's copy
// is dead) so the unrolled k-loop carries no divergent branch (no BSSY/BSYNC).
__global__ void __launch_bounds__(THREADS, 3)
spline_main_kernel(const float* __restrict__ c, const float* __restrict__ z,
                   const float* __restrict__ W, const float* __restrict__ b,
                   float* __restrict__ out) {
    extern __shared__ float sm[];
    float* Ws = sm;                                      // [49][4][36]
    float* As = sm + WS_F;                               // [49][66] transposed [k][row]
    unsigned long long* stash = (unsigned long long*)(sm + WS_F + AS_F);  // [17][256]

    const int t       = threadIdx.x;
    const int g       = blockIdx.x;                      // 0..7
    const int rowbase = blockIdx.y * BM;

    // Ws fill: y-coeff j of group gj at k (k=48 -> bias). [k][gj][j], pads 33-35.
    for (int idx = t; idx < KTOT * GPB * 33; idx += THREADS) {
        int k  = idx / (GPB * 33);
        int r  = idx - k * (GPB * 33);
        int gj = r / 33, j = r - gj * 33;
        int col = (g * GPB + gj) * 33 + j;
        float v = (k < 48) ? W[(size_t)k * 1056 + col] : b[col];
        Ws[k * WS_KS + gj * 36 + j] = v;
    }
    for (int idx = t; idx < KTOT * GPB; idx += THREADS)  // zero pad j=33 (pair-16 hi)
        Ws[(idx / GPB) * WS_KS + (idx % GPB) * 36 + 33] = 0.0f;

    // A tile transposed: k 0..31 = z[:,32:64], 32..47 = c, 48 = ones.
    for (int idx = t; idx < BM * 8; idx += THREADS) {
        int q = idx / BM, r = idx - q * BM;
        float4 v = *(const float4*)&z[(size_t)(rowbase + r) * 64 + 32 + q * 4];
        As[(q * 4 + 0) * AST + r] = v.x;
        As[(q * 4 + 1) * AST + r] = v.y;
        As[(q * 4 + 2) * AST + r] = v.z;
        As[(q * 4 + 3) * AST + r] = v.w;
    }
    for (int idx = t; idx < BM * 4; idx += THREADS) {
        int q = idx / BM, r = idx - q * BM;
        float4 v = *(const float4*)&c[(size_t)(rowbase + r) * 16 + q * 4];
        As[(32 + q * 4 + 0) * AST + r] = v.x;
        As[(32 + q * 4 + 1) * AST + r] = v.y;
        As[(32 + q * 4 + 2) * AST + r] = v.z;
        As[(32 + q * 4 + 3) * AST + r] = v.w;
    }
    for (int idx = t; idx < BM; idx += THREADS) As[48 * AST + idx] = 1.0f;
    __syncthreads();

    const int w_id = t >> 5, lane = t & 31;
    const int gw = w_id >> 1, rowhalf = w_id & 1;
    const int h1 = lane >> 4, l16 = lane & 15;
    const int lr = rowhalf * 32 + 2 * l16;     // GEMM rows lr, lr+1 (block-local)
    const int gn = g * GPB + gw;               // global spline index

    // spline input (this thread's single eval), hoisted to hide LDG latency
    const int myrow = rowbase + rowhalf * 32 + lane;
    float zin = z[(size_t)myrow * 64 + gn];

    // g==0 writes x[:, :32] = z2 from the As tile
    if (g == 0) {
        int r = t >> 2, c0 = (t & 3) * 8;
        float vv[8];
#pragma unroll
        for (int q = 0; q < 8; q++) vv[q] = As[(c0 + q) * AST + r];
        float4* dst = (float4*)&out[(size_t)(rowbase + r) * 64 + c0];
        dst[0] = make_float4(vv[0], vv[1], vv[2], vv[3]);
        dst[1] = make_float4(vv[4], vv[5], vv[6], vv[7]);
    }

    // ---- GEMM: 9 pairs x 2 rows, branch-free (slot 8 dead for h0) ----
    const float* wbase = Ws + gw * 36 + h1 * 16;   // h0: pairs 0-7; h1: pairs 8-15 (+16)
    unsigned long long acc0[9], acc1[9];
#pragma unroll
    for (int p = 0; p < 9; p++) { acc0[p] = 0ull; acc1[p] = 0ull; }

#pragma unroll 7
    for (int k = 0; k < KTOT; k++) {
        unsigned long long araw = *(const unsigned long long*)(As + k * AST + lr);
        unsigned long long ap0 = pack2(__uint_as_float((unsigned int)araw));
        unsigned long long ap1 = pack2(__uint_as_float((unsigned int)(araw >> 32)));
        const float* wrow = wbase + k * WS_KS;
#pragma unroll
        for (int i = 0; i < 4; i++) {       // 4x LDS.128, 2-address per warp
            ulonglong2 wv = *(const ulonglong2*)(wrow + i * 4);
            ffma2(acc0[2 * i],     ap0, wv.x);
            ffma2(acc1[2 * i],     ap1, wv.x);
            ffma2(acc0[2 * i + 1], ap0, wv.y);
            ffma2(acc1[2 * i + 1], ap1, wv.y);
        }
        // pair slot 8 (h1's pair 16): UNCONDITIONAL — h0 computes into a dead
        // slot (reads h1-half data, never stored). No divergent branch in loop.
        unsigned long long wt = *(const unsigned long long*)(wrow + 16);
        ffma2(acc0[8], ap0, wt);
        ffma2(acc1[8], ap1, wt);
    }

    // ---- stash: warp region w_id*32, WARP-LOCAL rows 2*l16, 2*l16+1 ----
    const int pbase = h1 * 8;                // h0 -> p 0-7, h1 -> p 8-15 (+16)
    unsigned long long* srow = stash + w_id * 32 + 2 * l16;
#pragma unroll
    for (int i = 0; i < 8; i++) {
        ulonglong2 v; v.x = acc0[i]; v.y = acc1[i];
        *(ulonglong2*)(srow + (pbase + i) * 256) = v;
    }
    if (h1) {                                // single branch, outside the loop
        ulonglong2 v; v.x = acc0[8]; v.y = acc1[8];
        *(ulonglong2*)(srow + 16 * 256) = v;
    }
    __syncwarp();

    // ---- spline: one eval per thread, pairs streamed from warp stash ----
    const unsigned long long* spr = stash + w_id * 32 + lane;
    float x, ld;
    ld = spline_eval([&](int p) { return spr[p * 256]; }, zin, x);

    // ---- staged epilogue (buf overlays stash after full-block barrier) ----
    __syncthreads();
    float2* buf = (float2*)stash;            // [4 groups][64 rows]
    buf[gw * BM + rowhalf * 32 + lane] = make_float2(x, ld);
    __syncthreads();

    {   // x writeout: 4 cols [32+g*4, +4) per row, 16B segments per 4 lanes
        int r = t >> 2, q = t & 3;
        out[(size_t)(rowbase + r) * 64 + 32 + g * GPB + q] = buf[q * BM + r].x;
    }
    if (t < BM) {                            // log_det: reduce 4 groups, 1 atomic/row
        float s = buf[t].y + buf[BM + t].y + buf[2 * BM + t].y + buf[3 * BM + t].y;
        atomicAdd(&out[(size_t)MROWS * 64 + rowbase + t], s);
    }
}

extern "C" void kernel_launch(void* const* d_in, const int* in_sizes, int n_in,
                              void* d_out, int out_size) {
    const float* c = (const float*)d_in[0];   // (65536, 16)
    const float* z = (const float*)d_in[1];   // (65536, 64)
    const float* W = (const float*)d_in[2];   // (48, 1056)
    const float* b = (const float*)d_in[3];   // (1056,)
    float* out = (float*)d_out;               // 65536*64 (x) + 65536 (log_det)

    cudaFuncSetAttribute(spline_main_kernel,
                         cudaFuncAttributeMaxDynamicSharedMemorySize, SMEM_BYTES);

    prep_kernel<<<(MROWS / 4 + 255) / 256, 256>>>(out);

    dim3 grid(NSPL / GPB, MROWS / BM);        // (8, 1024)
    spline_main_kernel<<<grid, THREADS, SMEM_BYTES>>>(c, z, W, b, out);
}

// round 17
// speedup vs baseline: 1.1615x; 1.1037x over previous
#include <cuda_runtime.h>
#include <cstdint>

// Problem constants
#define MROWS   65536
#define KDIM    48          // s_in = 32 + 16
#define NSPL    32          // spline groups per row
#define NB      33          // 2K+1 outputs per group (17 heights, 16 widths)
#define NPAD    36          // padded group width
#define NGRP    8           // spline groups per block (= warps per block)
#define BM      64          // rows per block
#define THREADS 256
#define WS_STRIDE (NGRP * NPAD)                 // 288 floats per k-row
#define AST     (BM + 2)                        // transposed A row: 64 rows + 2 pad
#define WS_F    (KDIM * WS_STRIDE)              // 13824
#define AS_F    (KDIM * AST)                    // 3168
#define BS_F    WS_STRIDE                       // 288
#define STASH_F (17 * THREADS * 2)              // 8704 floats (u64 slots)
#define LDBUF_F (NGRP * BM)                     // 512
#define SMEM_FLOATS (WS_F + AS_F + BS_F + STASH_F + LDBUF_F)
#define SMEM_BYTES  (SMEM_FLOATS * 4)           // 105984 B -> 2 blocks/SM

#define LOG2E 1.44269504088896340736f

// ---------- packed f32x2 helpers ----------
__device__ __forceinline__ unsigned long long pack2(float a) {
    unsigned long long r;
    asm("mov.b64 %0, {%1, %1};" : "=l"(r) : "f"(a));
    return r;
}
__device__ __forceinline__ void ffma2(unsigned long long& d,
                                      unsigned long long a,
                                      unsigned long long b) {
    asm("fma.rn.f32x2 %0, %1, %2, %0;" : "+l"(d) : "l"(a), "l"(b));
}

// raw MUFU ops (no domain-conversion FMULs)
__device__ __forceinline__ float ex2f(float x) {
    float r; asm("ex2.approx.ftz.f32 %0, %1;" : "=f"(r) : "f"(x)); return r;
}
__device__ __forceinline__ float lg2f(float x) {
    float r; asm("lg2.approx.ftz.f32 %0, %1;" : "=f"(r) : "f"(x)); return r;
}

// softplus in log2 domain: input y' = y*log2e (scaled in GEMM weights).
// Returns h_r = log2(1+e^y) + 0.001/ln2 ; the ln2 scale cancels in the
// height normalization, so downstream math uses h_r directly.
__device__ __forceinline__ float softplus_l2(float xp) {
    return lg2f(1.0f + ex2f(xp)) + 0.00144269504f;
}

// ---------- quadratic spline (per (m,n) pair), log2-domain MUFU ----------
// getacc(p) returns packed pair (y'[2p], y'[2p+1]) where y' = y*log2e;
// y[0..16]=unnorm heights, y[17..32]=unnorm widths, y[33]=0 (pad).
template <typename F>
__device__ __forceinline__ float spline_eval(F getacc, float input, float& x_out) {
    float h[17], w[16];

    // heights (log2-domain softplus; ln2 cancels in normalization)
#pragma unroll
    for (int p = 0; p < 8; p++) {
        unsigned long long v = getacc(p);
        h[2 * p]     = softplus_l2(__uint_as_float((unsigned int)v));
        h[2 * p + 1] = softplus_l2(__uint_as_float((unsigned int)(v >> 32)));
    }
    unsigned long long v8 = getacc(8);
    h[16] = softplus_l2(__uint_as_float((unsigned int)v8));

    // widths: e^y = exp2(y') — single MUFU each; softmax invariant
    float esum;
    w[0] = ex2f(__uint_as_float((unsigned int)(v8 >> 32)));
    esum = w[0];
#pragma unroll
    for (int p = 9; p <= 15; p++) {
        unsigned long long v = getacc(p);
        float e0 = ex2f(__uint_as_float((unsigned int)v));
        float e1 = ex2f(__uint_as_float((unsigned int)(v >> 32)));
        w[2 * p - 17] = e0;
        w[2 * p - 16] = e1;
        esum += e0 + e1;
    }
    {
        float e0 = ex2f(__uint_as_float((unsigned int)getacc(16)));
        w[15] = e0;
        esum += e0;
    }

    float inv = __fdividef(1.0f, esum);
#pragma unroll
    for (int i = 0; i < 16; i++) w[i] = 0.001f + 0.984f * (w[i] * inv);

    // area (0.5 and ln2 folded into divide) & normalized heights
    float area2 = 0.0f;
#pragma unroll
    for (int i = 0; i < 16; i++) area2 += (h[i] + h[i + 1]) * w[i];
    float hs = __fdividef(1.998f, area2);
#pragma unroll
    for (int i = 0; i < 17; i++) h[i] = 0.001f + h[i] * hs;

    // scan: cumsums + predicated bin select
    float L = 0.0f, C2 = 0.0f;
    float bl = 0.0f, bw = w[0], lcdf2 = 0.0f, hl = h[0], hr = h[1];
#pragma unroll
    for (int i = 1; i <= 15; i++) {
        L  += w[i - 1];
        C2 += (h[i - 1] + h[i]) * w[i - 1];
        if (input >= L) { bl = L; bw = w[i]; lcdf2 = C2; hl = h[i]; hr = h[i + 1]; }
    }

    float aq    = 0.5f * (hr - hl) * bw;
    float bq    = hl * bw;
    float alpha = __fdividef(input - bl, bw);
    float o = aq * alpha * alpha + bq * alpha + 0.5f * lcdf2;
    x_out = fminf(fmaxf(o, 0.0f), 1.0f);
    return __logf(alpha * (hr - hl) + hl);
}

// ---------- prep: zero log_det ----------
__global__ void prep_kernel(float* __restrict__ out) {
    int tid = blockIdx.x * blockDim.x + threadIdx.x;
    if (tid < MROWS / 4)
        ((float4*)(out + (size_t)MROWS * 64))[tid] = make_float4(0.f, 0.f, 0.f, 0.f);
}

// ---------- fused GEMM + spline (R11 skeleton + log2-domain weights) ----------
// WARP = GROUP: warp w owns spline group (g*8+w) for all 64 rows; all W smem
// loads warp-uniform (broadcast, 1 wf). Weights/bias pre-scaled by log2e.
__global__ void __launch_bounds__(THREADS, 2)
spline_main_kernel(const float* __restrict__ c, const float* __restrict__ z,
                   const float* __restrict__ W, const float* __restrict__ b,
                   float* __restrict__ out) {
    extern __shared__ float sm[];
    float* Ws = sm;                                   // [48][8][36]
    float* As = Ws + WS_F;                            // [48][66]  A transposed [k][row]
    float* bs = As + AS_F;                            // [8][36]
    unsigned long long* stash = (unsigned long long*)(bs + BS_F);   // [17][256]
    float* ldbuf = bs + BS_F + STASH_F;               // [8][64]

    const int t       = threadIdx.x;
    const int g       = blockIdx.x;                   // n-group block (0..3)
    const int rowbase = blockIdx.y * BM;

    // W slice scaled by log2e: cols [g*264, +264), float4 loads, swizzled STS.
    for (int idx = t; idx < KDIM * 66; idx += THREADS) {
        int k  = idx / 66;
        int c4 = idx - k * 66;
        float4 v = *(const float4*)&W[(size_t)k * 1056 + g * (NGRP * NB) + c4 * 4];
        float e[4] = {v.x * LOG2E, v.y * LOG2E, v.z * LOG2E, v.w * LOG2E};
#pragma unroll
        for (int q = 0; q < 4; q++) {
            int cc = c4 * 4 + q;
            int ln = cc / NB;
            int j  = cc - ln * NB;
            Ws[k * WS_STRIDE + ln * NPAD + j] = e[q];
        }
    }
    for (int idx = t; idx < KDIM * NGRP * 3; idx += THREADS) {  // zero pad j=33..35
        int k  = idx / (NGRP * 3);
        int r  = idx - k * (NGRP * 3);
        int ln = r / 3, j = 33 + (r - ln * 3);
        Ws[k * WS_STRIDE + ln * NPAD + j] = 0.0f;
    }
    // bias scaled by log2e (padded to 36)
    for (int idx = t; idx < WS_STRIDE; idx += THREADS) {
        int ln = idx / NPAD, j = idx - ln * NPAD;
        bs[idx] = (j < NB) ? b[g * (NGRP * NB) + ln * NB + j] * LOG2E : 0.0f;
    }
    // A tile transposed: k 0..31 = z[:,32:64], 32..47 = c.
    for (int idx = t; idx < BM * 8; idx += THREADS) {
        int q = idx / BM, r = idx - q * BM;
        float4 v = *(const float4*)&z[(size_t)(rowbase + r) * 64 + 32 + q * 4];
        As[(q * 4 + 0) * AST + r] = v.x;
        As[(q * 4 + 1) * AST + r] = v.y;
        As[(q * 4 + 2) * AST + r] = v.z;
        As[(q * 4 + 3) * AST + r] = v.w;
    }
    for (int idx = t; idx < BM * 4; idx += THREADS) {
        int q = idx / BM, r = idx - q * BM;
        float4 v = *(const float4*)&c[(size_t)(rowbase + r) * 16 + q * 4];
        As[(32 + q * 4 + 0) * AST + r] = v.x;
        As[(32 + q * 4 + 1) * AST + r] = v.y;
        As[(32 + q * 4 + 2) * AST + r] = v.z;
        As[(32 + q * 4 + 3) * AST + r] = v.w;
    }
    __syncthreads();

    // g==0 writes x[:, :32] = z2 from the As tile
    if (g == 0) {
        int r = t >> 2, c0 = (t & 3) * 8;
        float vv[8];
#pragma unroll
        for (int q = 0; q < 8; q++) vv[q] = As[(c0 + q) * AST + r];
        float4* dst = (float4*)&out[(size_t)(rowbase + r) * 64 + c0];
        dst[0] = make_float4(vv[0], vv[1], vv[2], vv[3]);
        dst[1] = make_float4(vv[4], vv[5], vv[6], vv[7]);
    }

    const int w_id = t >> 5;         // warp = local group in [0,8)
    const int lane = t & 31;
    const int r0 = lane * 2, r1 = r0 + 1;
    const int gn = g * NGRP + w_id;

    const float* wcol = Ws + w_id * NPAD;            // warp-uniform base
    const unsigned long long* b2 = (const unsigned long long*)(bs + w_id * NPAD);

    unsigned long long acc0[17], acc1[17];
#pragma unroll
    for (int p = 0; p < 17; p++) { acc0[p] = b2[p]; acc1[p] = b2[p]; }

#pragma unroll 4
    for (int k = 0; k < KDIM; k++) {
        unsigned long long araw = *(const unsigned long long*)(As + k * AST + r0);
        unsigned long long ap0 = pack2(__uint_as_float((unsigned int)araw));
        unsigned long long ap1 = pack2(__uint_as_float((unsigned int)(araw >> 32)));
        const float* wrow = wcol + k * WS_STRIDE;
#pragma unroll
        for (int p8 = 0; p8 < 8; p8++) {
            ulonglong2 wv = *(const ulonglong2*)(wrow + p8 * 4);
            ffma2(acc0[2 * p8],     ap0, wv.x);
            ffma2(acc1[2 * p8],     ap1, wv.x);
            ffma2(acc0[2 * p8 + 1], ap0, wv.y);
            ffma2(acc1[2 * p8 + 1], ap1, wv.y);
        }
        unsigned long long wt = *(const unsigned long long*)(wrow + 32);
        ffma2(acc0[16], ap0, wt);
        ffma2(acc1[16], ap1, wt);
    }

    const int row0 = rowbase + r0;
    const int row1 = rowbase + r1;
    float zin0 = z[(size_t)row0 * 64 + gn];
    float zin1 = z[(size_t)row1 * 64 + gn];

    // stash acc1 in dedicated SMEM (no barrier; own slots only)
#pragma unroll
    for (int p = 0; p < 17; p++) stash[p * THREADS + t] = acc1[p];

    float x0, x1v;
    float ld0 = spline_eval([&](int p) { return acc0[p]; }, zin0, x0);
    out[(size_t)row0 * 64 + 32 + gn] = x0;

    float ld1 = spline_eval([&](int p) { return stash[p * THREADS + t]; }, zin1, x1v);
    out[(size_t)row1 * 64 + 32 + gn] = x1v;

    // log_det: block reduce over 8 groups, then 64 atomics (4 g-blocks/row)
    *(float2*)&ldbuf[w_id * BM + r0] = make_float2(ld0, ld1);
    __syncthreads();
    if (t < BM) {
        float s = 0.0f;
#pragma unroll
        for (int w = 0; w < NGRP; w++) s += ldbuf[w * BM + t];
        atomicAdd(&out[(size_t)MROWS * 64 + rowbase + t], s);
    }
}

extern "C" void kernel_launch(void* const* d_in, const int* in_sizes, int n_in,
                              void* d_out, int out_size) {
    const float* c = (const float*)d_in[0];   // (65536, 16)
    const float* z = (const float*)d_in[1];   // (65536, 64)
    const float* W = (const float*)d_in[2];   // (48, 1056)
    const float* b = (const float*)d_in[3];   // (1056,)
    float* out = (float*)d_out;               // 65536*64 (x) + 65536 (log_det)

    cudaFuncSetAttribute(spline_main_kernel,
                         cudaFuncAttributeMaxDynamicSharedMemorySize, SMEM_BYTES);

    prep_kernel<<<(MROWS / 4 + 255) / 256, 256>>>(out);

    dim3 grid(NSPL / NGRP, MROWS / BM);       // (4, 1024)
    spline_main_kernel<<<grid, THREADS, SMEM_BYTES>>>(c, z, W, b, out);
}